// round 15
// baseline (speedup 1.0000x reference)
#include <cuda_runtime.h>
#include <math.h>

#define BB 64
#define QQ 2048
#define GG 64
#define CC 128
#define NT 512           // threads per block (both paths)
#define QT 64            // q-tile per fused block
#define NQB (QQ/QT)      // 32 q-blocks per batch
#define REPSL (QQ/NT)    // 4 columns per lsa thread

#define SCALE19 524288.0f           // 2^19 (bbox quant)
#define NEG2S21 (-4194304.0f)       // -2 * 2^21 (cls quant)
#define INF32 0x40000000

// ---------------- device scratch (static, no allocation) ----------------
__device__ int                g_cost[BB][GG][QQ];        // quantized cost, int32, 2^21
__device__ unsigned long long g_blockmin[BB][NQB][GG];   // per-tile row minima (packed)
__device__ double             g_part_cls[BB * NQB];
__device__ double             g_part_bbox[BB], g_part_xyz[BB], g_part_corr[BB];
__device__ int                g_part_acc[BB];
__device__ int                g_bctr[BB];                // per-batch tile counters
__device__ int                g_ctr;                     // lsa completion counter

__constant__ float c_normf[10] = {1.0f, 1.0f, 1.0f, 0.1f, 0.1f,
                                  0.1f, 1.0f, 1.0f, 0.1f, 0.1f};

// normalize+clip+quantize bbox element at scale 2^19 (R5-R13 verbatim)
__device__ __forceinline__ int quant_bbox19(float x, int k) {
    const double RD = 1.0 / (double)0.1f;
    const float Rh = (float)RD;
    const float Rl = (float)(RD - (double)Rh);
    float mh, ml;
    bool scaled = (k == 3 || k == 4 || k == 5 || k == 8 || k == 9);
    if (scaled) {
        mh = x * Rh;
        ml = fmaf(x, Rh, -mh);
        ml = fmaf(x, Rl, ml);
    } else { mh = x; ml = 0.0f; }
    if (mh > 100.0f)  { mh = 100.0f;  ml = 0.0f; }
    if (mh < -100.0f) { mh = -100.0f; ml = 0.0f; }
    return __float2int_rn(mh * SCALE19) + __float2int_rn(ml * SCALE19);
}

// branch-free focal: e=exp(-x), softplus(x)=x+log(1+e), softplus(-x)=log(1+e)
__device__ __forceinline__ float focal_neg_fast(float x) {
    float e = __expf(-x);
    float d = 1.0f + e;
    float p = __fdividef(1.0f, d);        // sigmoid(x)
    float lg = __logf(d);                 // log(1+e)
    return (x + lg) * (0.75f * (p * p));
}

__device__ __forceinline__ unsigned long long umin64(unsigned long long a,
                                                     unsigned long long b) {
    return (a < b) ? a : b;
}

// -------- shared-memory union --------
struct FusedSmem {
    float stile[32][CC];        // 16KB
    int sgq[GG][10];
    int slab[GG];
    int spn[QT][10];
    int smc[GG][QT + 1];        // 16.6KB
    double swred[16];
};
struct LsaSmem {
    long long spu[QQ + 1];      // (su[sp[j]]<<16)|sp[j], incrementally maintained
    short sp[QQ + 1];
    short sway[QQ + 1];
    int su[GG + 1];
    short srowarg[GG + 1];
    short spend[GG];
    short sinv[GG];
    unsigned long long sred[NT];
    unsigned rpv[16], rpj[16];
    double shb[16], shx[16], shc[16];
    int sha[16];
    double w0[16], w1[16], w2[16], w3[16], w4[16];
    int snpend, slast;
};
union MegaSmem { FusedSmem f; LsaSmem l; };

// ======== single kernel: blocks [0,2048) = tiles, [2048,2112) = per-batch LSA =====
__global__ __launch_bounds__(NT) void mega_kernel(const float* __restrict__ cs,
                                                  const float* __restrict__ bp,
                                                  const int* __restrict__ gl,
                                                  const float* __restrict__ gb,
                                                  float* __restrict__ out) {
    const int tid = threadIdx.x;
    const int lane = tid & 31, warp = tid >> 5;
    __shared__ MegaSmem sm;

    if (blockIdx.x < BB * NQB) {
        // ================= tile path (frozen cost arithmetic) ==================
        FusedSmem& F = sm.f;
        const int b = blockIdx.x >> 5;
        const int qblk = blockIdx.x & 31;
        const int qbase = qblk * QT;

        for (int u = tid; u < GG * 10; u += NT)
            F.sgq[u / 10][u % 10] = quant_bbox19(gb[b * GG * 10 + u], u % 10);
        if (tid < GG) F.slab[tid] = gl[b * GG + tid];
        for (int u = tid; u < QT * 10; u += NT)
            F.spn[u / 10][u % 10] =
                quant_bbox19(bp[((size_t)(b * QQ) + qbase) * 10 + u], u % 10);
        __syncthreads();

        const int tx = tid & 63;            // g index
        const int ty = tid >> 6;            // 0..7
        float acc0 = 0.0f, acc1 = 0.0f;

        for (int pass = 0; pass < 2; ++pass) {
            const float4* b4 =
                (const float4*)(cs + ((size_t)(b * QQ + qbase + pass * 32)) * CC);
#pragma unroll
            for (int k = 0; k < 2; ++k) {   // 1024 float4 / 512 threads
                int idx = tid + k * NT;
                float4 v = __ldg(b4 + idx);
                acc0 += focal_neg_fast(v.x);
                acc1 += focal_neg_fast(v.y);
                acc0 += focal_neg_fast(v.z);
                acc1 += focal_neg_fast(v.w);
                ((float4*)F.stile)[idx] = v;
            }
            __syncthreads();
            for (int qq = 0; qq < 4; ++qq) {
                int qloc = ty * 4 + qq;
                int ql = pass * 32 + qloc;
                float x = F.stile[qloc][F.slab[tx]];
                x = fminf(fmaxf(x, -20.0f), 20.0f);
                float e = __expf(-x);
                float p = __fdividef(1.0f, 1.0f + e);   // frozen cost path
                int cq = __float2int_rn(NEG2S21 * p);
                int l1 = 0;
#pragma unroll
                for (int k = 0; k < 10; ++k) {
                    int d = F.spn[ql][k] - F.sgq[tx][k];
                    l1 += (d < 0) ? -d : d;
                }
                F.smc[tx][ql] = cq + l1;
            }
            __syncthreads();
        }

        // coalesced writeback of the 64x64 tile
#pragma unroll
        for (int rep = 0; rep < 8; ++rep) {
            int idx = tid + NT * rep;
            int g = idx >> 6, ql = idx & 63;
            g_cost[b][g][qbase + ql] = F.smc[g][ql];
        }
        // per-tile row minima (packed sign-biased key) — same min as R13
        {
            int g = tid >> 3, sub = tid & 7;
            unsigned long long best = ~0ULL;
#pragma unroll
            for (int k = 0; k < 8; ++k) {
                int ql = sub * 8 + k;
                int v = F.smc[g][ql];
                unsigned long long key =
                    ((unsigned long long)((unsigned)v ^ 0x80000000u) << 12) |
                    (unsigned)(qbase + ql + 1);
                best = umin64(best, key);
            }
            best = umin64(best, __shfl_down_sync(0xffffffffu, best, 4));
            best = umin64(best, __shfl_down_sync(0xffffffffu, best, 2));
            best = umin64(best, __shfl_down_sync(0xffffffffu, best, 1));
            if (sub == 0) g_blockmin[b][qblk][g] = best;
        }
        // focal partial reduce
        double acc = (double)acc0 + (double)acc1;
        for (int off = 16; off; off >>= 1) acc += __shfl_down_sync(0xffffffffu, acc, off);
        if (lane == 0) F.swred[warp] = acc;
        __syncthreads();
        if (tid == 0) {
            double s = 0.0;
            for (int w = 0; w < 16; ++w) s += F.swred[w];
            g_part_cls[blockIdx.x] = s;
        }
        // release this tile
        __threadfence();
        __syncthreads();
        if (tid == 0) atomicAdd(&g_bctr[b], 1);
        return;
    }

    // ================= LSA path (R13 trajectory, spu-cached decisions) =========
    LsaSmem& L = sm.l;
    const int b = blockIdx.x - BB * NQB;

    // acquire this batch's 32 tiles
    if (tid == 0) {
        while (atomicAdd(&g_bctr[b], 0) < NQB) __nanosleep(128);
    }
    __syncthreads();
    __threadfence();

    // per-thread owned columns: j = 4*tid+1+rep
    int vreg[REPSL], minvr[REPSL], markr[REPSL], stampr[REPSL];
#pragma unroll
    for (int rep = 0; rep < REPSL; rep++) {
        vreg[rep] = 0; stampr[rep] = 0; minvr[rep] = 0; markr[rep] = 0;
    }
    for (int j = tid; j <= QQ; j += NT) L.sp[j] = 0;
    if (tid == 0) L.su[0] = 0;

    // --- Phase A: u_i = min over tiles of per-tile row minima (R13 verbatim) ---
    {
        int g = tid & 63, grp = tid >> 6;      // 8 groups of 4 tiles
        unsigned long long best = ~0ULL;
#pragma unroll
        for (int k = 0; k < 4; ++k)
            best = umin64(best, __ldg(&g_blockmin[b][grp * 4 + k][g]));
        L.sred[tid] = best;
    }
    __syncthreads();
    if (tid < GG) {
        unsigned long long m = L.sred[tid];
#pragma unroll
        for (int j = 1; j < 8; ++j) m = umin64(m, L.sred[tid + 64 * j]);
        L.su[tid + 1] = (int)((unsigned)(m >> 12) ^ 0x80000000u);
        L.srowarg[tid + 1] = (short)(m & 4095);
    }
    __syncthreads();

    const int* __restrict__ costb = &g_cost[b][0][0];

    // --- Phase B: greedy assignment on tight edges (R13 verbatim) ---
    if (tid == 0) {
        int np = 0;
        for (int i = 1; i <= GG; ++i) {
            int j = L.srowarg[i];
            if (L.sp[j] == 0) L.sp[j] = (short)i;
            else L.spend[np++] = (short)i;
        }
        L.snpend = np;
    }
    __syncthreads();

    // build spu cache once: (su[sp[j]]<<16)|sp[j]; su[0]=0 so free cols -> low16==0
#pragma unroll
    for (int rep = 0; rep < REPSL; rep++) {
        int j = 4 * tid + 1 + rep;
        int pj = L.sp[j];
        L.spu[j] = ((long long)L.su[pj] << 16) | (unsigned)pj;
    }
    __syncthreads();

    // --- Phase C: Dijkstra per pending row; 1 barrier/iter; spu decisions ---
    const int np = L.snpend;
    for (int pi = 0; pi < np; ++pi) {
        const int i = L.spend[pi];
        if (tid == 0) L.sp[0] = (short)i;
        int j0c = 0, i0 = i;
        int SD = 0, dpre = 0;
        int ui0 = L.su[i];                      // phase-start dual of pending row
        bool first = true;
        for (;;) {
            const int* arow = costb + (size_t)(i0 - 1) * QQ;
            int4 av4 = __ldg((const int4*)arow + tid);   // one LDG.128
            int av[REPSL] = {av4.x, av4.y, av4.z, av4.w};
            unsigned long long best = ~0ULL;
#pragma unroll
            for (int rep = 0; rep < REPSL; rep++) {
                int j = 4 * tid + 1 + rep;
                if (stampr[rep] == i) continue;
                if (j == j0c) { stampr[rep] = i; markr[rep] = SD; continue; }  // frontier
                int mv = first ? INF32 : (minvr[rep] - dpre);   // lazy minv-=delta
                int cur = av[rep] - ui0 - vreg[rep];
                if (cur < mv) { mv = cur; L.sway[j] = (short)j0c; }
                minvr[rep] = mv;
                unsigned long long pk =
                    ((unsigned long long)((unsigned)mv ^ 0x80000000u) << 12) |
                    (unsigned)j;                                // lex (value, j)
                best = umin64(best, pk);
            }
            // warp argmin via REDUX: exact lex (value, j) min, first-occurrence
            {
                unsigned mv32 = (unsigned)(best >> 12);
                unsigned j32  = (unsigned)(best & 4095);
                unsigned m1 = __reduce_min_sync(0xffffffffu, mv32);
                unsigned jc = (mv32 == m1) ? j32 : 0xffffffffu;
                unsigned m2 = __reduce_min_sync(0xffffffffu, jc);
                if (lane == 0) { L.rpv[warp] = m1; L.rpj[warp] = m2; }
            }
            __syncthreads();                    // the ONE barrier
            // cross-warp min: sentinel lanes + 2 REDUX (same lex min as u64 chain)
            unsigned vv = (lane < 16) ? L.rpv[lane] : 0xffffffffu;
            unsigned jj = (lane < 16) ? L.rpj[lane] : 0xffffffffu;
            unsigned m1 = __reduce_min_sync(0xffffffffu, vv);
            unsigned jc2 = (vv == m1) ? jj : 0xffffffffu;
            unsigned j1u = __reduce_min_sync(0xffffffffu, jc2);
            int d = (int)(m1 ^ 0x80000000u);
            int j1 = (int)j1u;
            SD += d;
            dpre = d;
            long long pk1 = L.spu[j1];          // ONE LDS: (su[sp[j1]], sp[j1])
            int pj1 = (int)(pk1 & 0xffff);
            if (pj1 == 0) { j0c = j1; break; }  // reached free column
            ui0 = (int)(pk1 >> 16);             // su snapshot, frozen within phase
            j0c = j1;
            i0 = pj1;
            first = false;
        }
        // deferred u/v updates over own used columns (pre-augment sp; same values)
#pragma unroll
        for (int rep = 0; rep < REPSL; rep++) {
            if (stampr[rep] == i) {
                int adj = SD - markr[rep];
                vreg[rep] -= adj;
                int j = 4 * tid + 1 + rep;
                int r = L.sp[j];                // distinct rows across threads
                int sun = L.su[r] + adj;
                L.su[r] = sun;
                L.spu[j] = ((long long)sun << 16) | (unsigned)r;
            }
        }
        if (tid == 0) L.su[i] += SD;            // artificial column 0 (sp[0]=i, mark 0)
        __syncthreads();                        // settle sway + su/spu writes
        if (tid == 0) {                         // augment along way[] + spu fix
            int j0 = j0c;
            while (j0) {
                int jn = L.sway[j0];
                int rn = L.sp[jn];
                L.sp[j0] = (short)rn;
                L.spu[j0] = ((long long)L.su[rn] << 16) | (unsigned)rn;
                j0 = jn;
            }
        }
        __syncthreads();
    }

    // --- build g -> q map ---
#pragma unroll
    for (int rep = 0; rep < REPSL; rep++) {
        int j = 4 * tid + 1 + rep;
        int pj = L.sp[j];
        if (pj) L.sinv[pj - 1] = (short)(j - 1);
    }
    __syncthreads();

    // --- fused bbox losses + argmax acc + focal correction (warp per g) ---
    double sb = 0.0, sx = 0.0, corr = 0.0;
    int ok = 0;
#pragma unroll
    for (int gw = 0; gw < 4; ++gw) {
        int g = gw * 16 + warp;
        int q = L.sinv[g];
        int lab = gl[b * GG + g];
        const float* r = cs + (size_t)(b * QQ + q) * CC;

        float bestv = -INFINITY; int bi = 0;
#pragma unroll
        for (int k = 0; k < 4; ++k) {
            int c = lane + 32 * k;
            float v = __ldg(r + c);
            if (v > bestv) { bestv = v; bi = c; }
        }
        for (int off = 16; off; off >>= 1) {
            float ov = __shfl_down_sync(0xffffffffu, bestv, off);
            int   oi = __shfl_down_sync(0xffffffffu, bi, off);
            if (ov > bestv || (ov == bestv && oi < bi)) { bestv = ov; bi = oi; }
        }
        if (lane == 0) ok += (bi == lab) ? 1 : 0;

        if (lane < 10) {
            float a  = bp[(size_t)(b * QQ + q) * 10 + lane];
            float c2 = gb[(size_t)(b * GG + g) * 10 + lane];
            float nr = c_normf[lane];
            sb += (double)fabsf(a / nr - c2 / nr);
            if (lane < 3) sx += (double)fabsf(a - c2);
        }
        if (lane == 0) {            // correction: pos - neg (same formula as tiles)
            float x = __ldg(r + lab);
            float e = __expf(-x);
            float d0 = 1.0f + e;
            float p = __fdividef(1.0f, d0);
            float lg = __logf(d0);
            float neg = (x + lg) * (0.75f * (p * p));
            float om = 1.0f - p;
            float pos = lg * (0.25f * (om * om));
            corr += (double)pos - (double)neg;
        }
    }
    for (int off = 16; off; off >>= 1) {
        sb   += __shfl_down_sync(0xffffffffu, sb, off);
        sx   += __shfl_down_sync(0xffffffffu, sx, off);
        corr += __shfl_down_sync(0xffffffffu, corr, off);
        ok   += __shfl_down_sync(0xffffffffu, ok, off);
    }
    if (lane == 0) { L.shb[warp] = sb; L.shx[warp] = sx; L.shc[warp] = corr; L.sha[warp] = ok; }
    __syncthreads();
    if (tid == 0) {
        double tb = 0, tx2 = 0, tc = 0; int ta = 0;
        for (int w2 = 0; w2 < 16; ++w2) { tb += L.shb[w2]; tx2 += L.shx[w2]; tc += L.shc[w2]; ta += L.sha[w2]; }
        g_part_bbox[b] = tb; g_part_xyz[b] = tx2; g_part_corr[b] = tc; g_part_acc[b] = ta;
    }

    // --- last LSA block: final combine + counter resets ---
    __threadfence();
    __syncthreads();
    if (tid == 0) L.slast = (atomicAdd(&g_ctr, 1) == BB - 1) ? 1 : 0;
    __syncthreads();
    if (L.slast) {
        __threadfence();
        double s = 0.0;
        for (int k = tid; k < BB * NQB; k += NT) s += g_part_cls[k];
        double c2 = 0.0, b2 = 0.0, x2 = 0.0, a2 = 0.0;
        if (tid < BB) {
            c2 = g_part_corr[tid]; b2 = g_part_bbox[tid]; x2 = g_part_xyz[tid];
            a2 = (double)g_part_acc[tid];
        }
        for (int off = 16; off; off >>= 1) {
            s  += __shfl_down_sync(0xffffffffu, s, off);
            c2 += __shfl_down_sync(0xffffffffu, c2, off);
            b2 += __shfl_down_sync(0xffffffffu, b2, off);
            x2 += __shfl_down_sync(0xffffffffu, x2, off);
            a2 += __shfl_down_sync(0xffffffffu, a2, off);
        }
        if (lane == 0) { L.w0[warp] = s; L.w1[warp] = c2; L.w2[warp] = b2; L.w3[warp] = x2; L.w4[warp] = a2; }
        __syncthreads();
        if (tid == 0) {
            double ts = 0, tc = 0, tb = 0, tx = 0, ta = 0;
            for (int w5 = 0; w5 < 16; ++w5) {
                ts += L.w0[w5]; tc += L.w1[w5]; tb += L.w2[w5]; tx += L.w3[w5]; ta += L.w4[w5];
            }
            out[0] = (float)((ts + tc) / 4096.0);
            out[1] = (float)(tb / 40960.0);
            out[2] = 64.0f;
            out[3] = (float)(ta / 4096.0);
            out[4] = (float)(tx / 12288.0);
            for (int k = 0; k < BB; ++k) g_bctr[k] = 0;   // reset for replay
            g_ctr = 0;
        }
    }
}

// ---------------- launch ----------------
extern "C" void kernel_launch(void* const* d_in, const int* in_sizes, int n_in,
                              void* d_out, int out_size) {
    const float* cs = (const float*)d_in[0];   // (64,2048,128) f32
    const float* bp = (const float*)d_in[1];   // (64,2048,10)  f32
    const int*   gl = (const int*)d_in[2];     // (64,64)       i32
    const float* gb = (const float*)d_in[3];   // (64,64,10)    f32
    float* out = (float*)d_out;

    mega_kernel<<<BB * NQB + BB, NT>>>(cs, bp, gl, gb, out);
}

// round 16
// speedup vs baseline: 1.2730x; 1.2730x over previous
#include <cuda_runtime.h>
#include <math.h>

#define BB 64
#define QQ 2048
#define GG 64
#define CC 128
#define NT 256           // fused threads
#define QT 64            // q-tile per fused block
#define NQB (QQ/QT)      // 32 q-blocks per batch
#define NTL 512          // lsa threads
#define REPSL (QQ/NTL)   // 4

#define SCALE19 524288.0f           // 2^19 (bbox quant)
#define NEG2S21 (-4194304.0f)       // -2 * 2^21 (cls quant)
#define INF32 0x40000000

// ---------------- device scratch (static, no allocation) ----------------
__device__ int                g_cost[BB][GG][QQ];        // quantized cost, int32, 2^21
__device__ unsigned long long g_blockmin[BB][NQB][GG];   // per-tile row minima (packed)
__device__ double             g_part_cls[BB * NQB];
__device__ double             g_part_bbox[BB], g_part_xyz[BB], g_part_corr[BB];
__device__ int                g_part_acc[BB];
__device__ int                g_ctr;                     // lsa completion counter

__constant__ float c_normf[10] = {1.0f, 1.0f, 1.0f, 0.1f, 0.1f,
                                  0.1f, 1.0f, 1.0f, 0.1f, 0.1f};

// normalize+clip+quantize bbox element at scale 2^19 (R5-R13 verbatim)
__device__ __forceinline__ int quant_bbox19(float x, int k) {
    const double RD = 1.0 / (double)0.1f;
    const float Rh = (float)RD;
    const float Rl = (float)(RD - (double)Rh);
    float mh, ml;
    bool scaled = (k == 3 || k == 4 || k == 5 || k == 8 || k == 9);
    if (scaled) {
        mh = x * Rh;
        ml = fmaf(x, Rh, -mh);
        ml = fmaf(x, Rl, ml);
    } else { mh = x; ml = 0.0f; }
    if (mh > 100.0f)  { mh = 100.0f;  ml = 0.0f; }
    if (mh < -100.0f) { mh = -100.0f; ml = 0.0f; }
    return __float2int_rn(mh * SCALE19) + __float2int_rn(ml * SCALE19);
}

// branch-free focal: e=exp(-x), softplus(x)=x+log(1+e), softplus(-x)=log(1+e)
__device__ __forceinline__ float focal_neg_fast(float x) {
    float e = __expf(-x);
    float d = 1.0f + e;
    float p = __fdividef(1.0f, d);        // sigmoid(x)
    float lg = __logf(d);                 // log(1+e)
    return (x + lg) * (0.75f * (p * p));
}

__device__ __forceinline__ unsigned long long umin64(unsigned long long a,
                                                     unsigned long long b) {
    return (a < b) ? a : b;
}

// ======== K1: fused cost tile (smem-staged cs) + row minima + focal (R13 verbatim) =
__global__ __launch_bounds__(NT) void fused_kernel(const float* __restrict__ cs,
                                                   const float* __restrict__ bp,
                                                   const int* __restrict__ gl,
                                                   const float* __restrict__ gb) {
    const int b = blockIdx.x >> 5;
    const int qblk = blockIdx.x & 31;
    const int qbase = qblk * QT;
    const int tid = threadIdx.x;
    const int lane = tid & 31, warp = tid >> 5;

    __shared__ float stile[32][CC];         // 16KB: half the q-tile of cs
    __shared__ int sgq[GG][10];
    __shared__ int slab[GG];
    __shared__ int spn[QT][10];
    __shared__ int smc[GG][QT + 1];         // stride 65 -> conflict-free
    __shared__ double swred[8];

    for (int u = tid; u < GG * 10; u += NT)
        sgq[u / 10][u % 10] = quant_bbox19(gb[b * GG * 10 + u], u % 10);
    if (tid < GG) slab[tid] = gl[b * GG + tid];
    for (int u = tid; u < QT * 10; u += NT)
        spn[u / 10][u % 10] = quant_bbox19(bp[((size_t)(b * QQ) + qbase) * 10 + u], u % 10);
    __syncthreads();

    const int tx = tid & 63;                // g index
    const int ty = tid >> 6;                // 0..3
    float acc0 = 0.0f, acc1 = 0.0f;         // focal partials

    for (int pass = 0; pass < 2; ++pass) {
        const float4* b4 =
            (const float4*)(cs + ((size_t)(b * QQ + qbase + pass * 32)) * CC);
#pragma unroll
        for (int k = 0; k < 4; ++k) {       // 1024 float4 / 256 threads
            int idx = tid + k * NT;
            float4 v = __ldg(b4 + idx);
            acc0 += focal_neg_fast(v.x);
            acc1 += focal_neg_fast(v.y);
            acc0 += focal_neg_fast(v.z);
            acc1 += focal_neg_fast(v.w);
            ((float4*)stile)[idx] = v;      // [ql][c4], conflict-free
        }
        __syncthreads();

        // cost for these 32 rows; gather from smem (frozen arithmetic)
        for (int qq = 0; qq < 8; ++qq) {
            int qloc = ty * 8 + qq;
            int ql = pass * 32 + qloc;
            float x = stile[qloc][slab[tx]];
            x = fminf(fmaxf(x, -20.0f), 20.0f);
            float e = __expf(-x);
            float p = __fdividef(1.0f, 1.0f + e);
            int cq = __float2int_rn(NEG2S21 * p);
            int l1 = 0;
#pragma unroll
            for (int k = 0; k < 10; ++k) {
                int d = spn[ql][k] - sgq[tx][k];
                l1 += (d < 0) ? -d : d;
            }
            smc[tx][ql] = cq + l1;
        }
        __syncthreads();
    }

    // coalesced writeback of the 64x64 tile
#pragma unroll
    for (int rep = 0; rep < 16; ++rep) {
        int idx = tid + NT * rep;
        int g = idx >> 6, ql = idx & 63;
        g_cost[b][g][qbase + ql] = smc[g][ql];
    }
    // per-tile row minima (packed sign-biased key) — R10 verbatim
    {
        int g = tid >> 2, sub = tid & 3;
        unsigned long long best = ~0ULL;
#pragma unroll
        for (int k = 0; k < 16; ++k) {
            int ql = sub * 16 + k;
            int v = smc[g][ql];
            unsigned long long key =
                ((unsigned long long)((unsigned)v ^ 0x80000000u) << 12) |
                (unsigned)(qbase + ql + 1);
            best = umin64(best, key);
        }
        best = umin64(best, __shfl_down_sync(0xffffffffu, best, 2));
        best = umin64(best, __shfl_down_sync(0xffffffffu, best, 1));
        if (sub == 0) g_blockmin[b][qblk][g] = best;
    }

    // focal partial reduce
    double acc = (double)acc0 + (double)acc1;
    for (int off = 16; off; off >>= 1) acc += __shfl_down_sync(0xffffffffu, acc, off);
    if (lane == 0) swred[warp] = acc;
    __syncthreads();
    if (tid == 0) {
        double s = 0.0;
        for (int w = 0; w < 8; ++w) s += swred[w];
        g_part_cls[blockIdx.x] = s;
    }
}

// ======== K2: JV LSA (R13 trajectory; spu cache + REDUX reduces) ==========
__global__ __launch_bounds__(NTL) void lsa_kernel(const float* __restrict__ cs,
                                                  const float* __restrict__ bp,
                                                  const int* __restrict__ gl,
                                                  const float* __restrict__ gb,
                                                  float* __restrict__ out) {
    const int b = blockIdx.x, tid = threadIdx.x;
    const int lane = tid & 31, warp = tid >> 5;

    __shared__ long long spu[QQ + 1];       // (su[sp[j]]<<16)|sp[j], incremental
    __shared__ short sp[QQ + 1];
    __shared__ short sway[QQ + 1];
    __shared__ int su[GG + 1];
    __shared__ short srowarg[GG + 1];
    __shared__ short spend[GG];
    __shared__ short sinv[GG];
    __shared__ unsigned long long sred[NTL];
    __shared__ unsigned rpv[16], rpj[16];
    __shared__ int snpend, slast;

    // per-thread owned columns: j = 4*tid+1+rep (contiguous -> int4 loads)
    int vreg[REPSL], minvr[REPSL], markr[REPSL], stampr[REPSL];
#pragma unroll
    for (int rep = 0; rep < REPSL; rep++) {
        vreg[rep] = 0; stampr[rep] = 0; minvr[rep] = 0; markr[rep] = 0;
    }
    for (int j = tid; j <= QQ; j += NTL) sp[j] = 0;
    if (tid == 0) su[0] = 0;

    // --- Phase A: u_i = min over tiles of per-tile row minima (R13 verbatim) ---
    {
        int g = tid & 63, grp = tid >> 6;      // 8 groups of 4 tiles
        unsigned long long best = ~0ULL;
#pragma unroll
        for (int k = 0; k < 4; ++k)
            best = umin64(best, __ldg(&g_blockmin[b][grp * 4 + k][g]));
        sred[tid] = best;
    }
    __syncthreads();
    if (tid < GG) {
        unsigned long long m = sred[tid];
#pragma unroll
        for (int j = 1; j < 8; ++j) m = umin64(m, sred[tid + 64 * j]);
        su[tid + 1] = (int)((unsigned)(m >> 12) ^ 0x80000000u);
        srowarg[tid + 1] = (short)(m & 4095);
    }
    __syncthreads();

    const int* __restrict__ costb = &g_cost[b][0][0];

    // --- Phase B: greedy assignment on tight edges (R13 verbatim) ---
    if (tid == 0) {
        int np = 0;
        for (int i = 1; i <= GG; ++i) {
            int j = srowarg[i];
            if (sp[j] == 0) sp[j] = (short)i;
            else spend[np++] = (short)i;
        }
        snpend = np;
    }
    __syncthreads();

    // build spu cache once: (su[sp[j]]<<16)|sp[j]; su[0]=0 so free cols -> low16==0
#pragma unroll
    for (int rep = 0; rep < REPSL; rep++) {
        int j = 4 * tid + 1 + rep;
        int pj = sp[j];
        spu[j] = ((long long)su[pj] << 16) | (unsigned)pj;
    }
    __syncthreads();

    // --- Phase C: Dijkstra per pending row; 1 barrier/iter; spu decisions ---
    // Key set, lex min, dual values identical to R13 => identical trajectory.
    const int np = snpend;
    for (int pi = 0; pi < np; ++pi) {
        const int i = spend[pi];
        if (tid == 0) sp[0] = (short)i;
        int j0c = 0, i0 = i;
        int SD = 0, dpre = 0;
        int ui0 = su[i];                        // phase-start dual of pending row
        bool first = true;
        for (;;) {
            const int* arow = costb + (size_t)(i0 - 1) * QQ;
            int4 av4 = __ldg((const int4*)arow + tid);   // one LDG.128
            int av[REPSL] = {av4.x, av4.y, av4.z, av4.w};
            unsigned long long best = ~0ULL;
#pragma unroll
            for (int rep = 0; rep < REPSL; rep++) {
                int j = 4 * tid + 1 + rep;
                if (stampr[rep] == i) continue;
                if (j == j0c) { stampr[rep] = i; markr[rep] = SD; continue; }  // frontier
                int mv = first ? INF32 : (minvr[rep] - dpre);   // lazy minv-=delta
                int cur = av[rep] - ui0 - vreg[rep];
                if (cur < mv) { mv = cur; sway[j] = (short)j0c; }
                minvr[rep] = mv;
                unsigned long long pk =
                    ((unsigned long long)((unsigned)mv ^ 0x80000000u) << 12) |
                    (unsigned)j;                                // lex (value, j)
                best = umin64(best, pk);
            }
            // warp argmin via REDUX: exact lex (value, j) min, first-occurrence
            {
                unsigned mv32 = (unsigned)(best >> 12);
                unsigned j32  = (unsigned)(best & 4095);
                unsigned m1 = __reduce_min_sync(0xffffffffu, mv32);
                unsigned jc = (mv32 == m1) ? j32 : 0xffffffffu;
                unsigned m2 = __reduce_min_sync(0xffffffffu, jc);
                if (lane == 0) { rpv[warp] = m1; rpj[warp] = m2; }
            }
            __syncthreads();                    // the ONE barrier
            // cross-warp min: sentinel lanes + 2 REDUX (same lex min)
            unsigned vv = (lane < 16) ? rpv[lane] : 0xffffffffu;
            unsigned jj = (lane < 16) ? rpj[lane] : 0xffffffffu;
            unsigned m1 = __reduce_min_sync(0xffffffffu, vv);
            unsigned jc2 = (vv == m1) ? jj : 0xffffffffu;
            unsigned j1u = __reduce_min_sync(0xffffffffu, jc2);
            int d = (int)(m1 ^ 0x80000000u);
            int j1 = (int)j1u;
            SD += d;
            dpre = d;
            long long pk1 = spu[j1];            // ONE LDS: (su[sp[j1]], sp[j1])
            int pj1 = (int)(pk1 & 0xffff);
            if (pj1 == 0) { j0c = j1; break; }  // reached free column
            ui0 = (int)(pk1 >> 16);             // su snapshot, frozen within phase
            j0c = j1;
            i0 = pj1;
            first = false;
        }
        // deferred u/v updates over own used columns (pre-augment sp; same values)
#pragma unroll
        for (int rep = 0; rep < REPSL; rep++) {
            if (stampr[rep] == i) {
                int adj = SD - markr[rep];
                vreg[rep] -= adj;
                int j = 4 * tid + 1 + rep;
                int r = sp[j];                  // distinct rows across threads
                int sun = su[r] + adj;
                su[r] = sun;
                spu[j] = ((long long)sun << 16) | (unsigned)r;
            }
        }
        if (tid == 0) su[i] += SD;              // artificial column 0 (sp[0]=i, mark 0)
        __syncthreads();                        // settle sway + su/spu writes
        if (tid == 0) {                         // augment along way[] + spu fix
            int j0 = j0c;
            while (j0) {
                int jn = sway[j0];
                int rn = sp[jn];
                sp[j0] = (short)rn;
                spu[j0] = ((long long)su[rn] << 16) | (unsigned)rn;
                j0 = jn;
            }
        }
        __syncthreads();
    }

    // --- build g -> q map ---
#pragma unroll
    for (int rep = 0; rep < REPSL; rep++) {
        int j = 4 * tid + 1 + rep;
        int pj = sp[j];
        if (pj) sinv[pj - 1] = (short)(j - 1);
    }
    __syncthreads();

    // --- fused bbox losses + argmax acc + focal correction (warp per g) ---
    double sb = 0.0, sx = 0.0, corr = 0.0;
    int ok = 0;
#pragma unroll
    for (int gw = 0; gw < 4; ++gw) {
        int g = gw * 16 + warp;
        int q = sinv[g];
        int lab = gl[b * GG + g];
        const float* r = cs + (size_t)(b * QQ + q) * CC;

        float bestv = -INFINITY; int bi = 0;
#pragma unroll
        for (int k = 0; k < 4; ++k) {
            int c = lane + 32 * k;
            float v = __ldg(r + c);
            if (v > bestv) { bestv = v; bi = c; }
        }
        for (int off = 16; off; off >>= 1) {
            float ov = __shfl_down_sync(0xffffffffu, bestv, off);
            int   oi = __shfl_down_sync(0xffffffffu, bi, off);
            if (ov > bestv || (ov == bestv && oi < bi)) { bestv = ov; bi = oi; }
        }
        if (lane == 0) ok += (bi == lab) ? 1 : 0;

        if (lane < 10) {
            float a  = bp[(size_t)(b * QQ + q) * 10 + lane];
            float c2 = gb[(size_t)(b * GG + g) * 10 + lane];
            float nr = c_normf[lane];
            sb += (double)fabsf(a / nr - c2 / nr);
            if (lane < 3) sx += (double)fabsf(a - c2);
        }
        if (lane == 0) {            // correction: pos - neg (same formula as fused)
            float x = __ldg(r + lab);
            float e = __expf(-x);
            float d0 = 1.0f + e;
            float p = __fdividef(1.0f, d0);
            float lg = __logf(d0);
            float neg = (x + lg) * (0.75f * (p * p));
            float om = 1.0f - p;
            float pos = lg * (0.25f * (om * om));
            corr += (double)pos - (double)neg;
        }
    }
    for (int off = 16; off; off >>= 1) {
        sb   += __shfl_down_sync(0xffffffffu, sb, off);
        sx   += __shfl_down_sync(0xffffffffu, sx, off);
        corr += __shfl_down_sync(0xffffffffu, corr, off);
        ok   += __shfl_down_sync(0xffffffffu, ok, off);
    }
    __shared__ double shb[16], shx[16], shc[16];
    __shared__ int sha[16];
    if (lane == 0) { shb[warp] = sb; shx[warp] = sx; shc[warp] = corr; sha[warp] = ok; }
    __syncthreads();
    if (tid == 0) {
        double tb = 0, tx2 = 0, tc = 0; int ta = 0;
        for (int w2 = 0; w2 < 16; ++w2) { tb += shb[w2]; tx2 += shx[w2]; tc += shc[w2]; ta += sha[w2]; }
        g_part_bbox[b] = tb; g_part_xyz[b] = tx2; g_part_corr[b] = tc; g_part_acc[b] = ta;
    }

    // --- last block: final combine + counter reset ---
    __threadfence();
    __syncthreads();
    if (tid == 0) slast = (atomicAdd(&g_ctr, 1) == BB - 1) ? 1 : 0;
    __syncthreads();
    if (slast) {
        __threadfence();
        double s = 0.0;
        for (int k = tid; k < BB * NQB; k += NTL) s += g_part_cls[k];
        double c2 = 0.0, b2 = 0.0, x2 = 0.0, a2 = 0.0;
        if (tid < BB) {
            c2 = g_part_corr[tid]; b2 = g_part_bbox[tid]; x2 = g_part_xyz[tid];
            a2 = (double)g_part_acc[tid];
        }
        for (int off = 16; off; off >>= 1) {
            s  += __shfl_down_sync(0xffffffffu, s, off);
            c2 += __shfl_down_sync(0xffffffffu, c2, off);
            b2 += __shfl_down_sync(0xffffffffu, b2, off);
            x2 += __shfl_down_sync(0xffffffffu, x2, off);
            a2 += __shfl_down_sync(0xffffffffu, a2, off);
        }
        __shared__ double w0[16], w1[16], w2[16], w3[16], w4[16];
        if (lane == 0) { w0[warp] = s; w1[warp] = c2; w2[warp] = b2; w3[warp] = x2; w4[warp] = a2; }
        __syncthreads();
        if (tid == 0) {
            double ts = 0, tc = 0, tb = 0, tx = 0, ta = 0;
            for (int w5 = 0; w5 < 16; ++w5) {
                ts += w0[w5]; tc += w1[w5]; tb += w2[w5]; tx += w3[w5]; ta += w4[w5];
            }
            out[0] = (float)((ts + tc) / 4096.0);
            out[1] = (float)(tb / 40960.0);
            out[2] = 64.0f;
            out[3] = (float)(ta / 4096.0);
            out[4] = (float)(tx / 12288.0);
            g_ctr = 0;                       // reset for next graph replay
        }
    }
}

// ---------------- launch ----------------
extern "C" void kernel_launch(void* const* d_in, const int* in_sizes, int n_in,
                              void* d_out, int out_size) {
    const float* cs = (const float*)d_in[0];   // (64,2048,128) f32
    const float* bp = (const float*)d_in[1];   // (64,2048,10)  f32
    const int*   gl = (const int*)d_in[2];     // (64,64)       i32
    const float* gb = (const float*)d_in[3];   // (64,64,10)    f32
    float* out = (float*)d_out;

    fused_kernel<<<BB * NQB, NT>>>(cs, bp, gl, gb);
    lsa_kernel<<<BB, NTL>>>(cs, bp, gl, gb, out);
}